// round 15
// baseline (speedup 1.0000x reference)
#include <cuda_runtime.h>
#include <cuda_fp16.h>
#include <stdint.h>
#include <math.h>

// ---------------------------------------------------------------------------
// QRNN on sm_103. ONE persistent kernel does: phase0 fp32->fp16 conversion
// (dynamic items), phase1 fp16 HMMA GEMM (128x128 tiles, 8 warps x 64x32,
// 2 CTA/SM, dynamic tiles gated on conversion), phase2 fo-pool scan pass1.
// pass2+3 fused as a second kernel. Counters self-reset (graph-safe).
// ---------------------------------------------------------------------------

#define B_   8
#define T_   4096
#define D_   512
#define U_   512
#define N3_  1536
#define K_   1024
#define M_   (B_*T_)

#define BM 128
#define BN 128
#define BK 32
#define KCHUNKS (K_/BK)          // 32
#define STAGES 4
#define NBLK (N3_/BN)            // 12
#define MBLK (M_/BM)             // 256
#define NT_TILES (NBLK*MBLK)     // 3072
#define NCTA 304
#define NTHREADS 256

#define ROWB        80
#define MAT_BYTES   (128*ROWB)                // 10240
#define STAGE_BYTES (2*MAT_BYTES)             // 20480 (X, W)
#define SMEM_TOTAL  (STAGES*STAGE_BYTES)      // 81920

#define NCHUNK 64
#define TCHUNK (T_/NCHUNK)       // 64
#define U2 (U_/2)                // 256
#define N3H2 (N3_/2)             // 768
#define NP1 (B_*NCHUNK)          // 512

#define KBLKS ((N3_/32)*(K_/32))   // 1536 W-transpose items
#define NCONV (KBLKS + MBLK)       // + 256 x-block items

// ---- scratch ----------------------------------------------------------------
__device__ __half g_gatesh[(size_t)M_ * N3_];
__device__ float g_cend [B_*NCHUNK*U_];
__device__ float g_P    [B_*NCHUNK*U_];
__device__ __half g_xh[(size_t)M_ * D_];
__device__ __half g_wh[(size_t)N3_ * K_];
__device__ int g_conv_ctr;
__device__ int g_tile_ctr;
__device__ unsigned g_p1_ctr;
__device__ int g_w_cnt;
__device__ int g_x_done[MBLK];
__device__ int g_mb_done[MBLK];
__device__ int g_exit_ctr;

// ---- helpers ------------------------------------------------------------------
__device__ __forceinline__ uint32_t smem_u32(const void* p) {
    uint32_t r;
    asm("{ .reg .u64 t; cvta.to.shared.u64 t, %1; cvt.u32.u64 %0, t; }" : "=r"(r) : "l"(p));
    return r;
}
__device__ __forceinline__ void cp16(uint32_t dst, const void* src, int ssize) {
    asm volatile("cp.async.cg.shared.global [%0], [%1], 16, %2;"
                 :: "r"(dst), "l"(src), "r"(ssize) : "memory");
}
__device__ __forceinline__ void cp_commit() {
    asm volatile("cp.async.commit_group;" ::: "memory");
}
__device__ __forceinline__ void ldm_x4(uint32_t* r, uint32_t addr) {
    asm volatile("ldmatrix.sync.aligned.m8n8.x4.shared.b16 {%0,%1,%2,%3}, [%4];"
                 : "=r"(r[0]), "=r"(r[1]), "=r"(r[2]), "=r"(r[3]) : "r"(addr));
}
__device__ __forceinline__ void mma16816(float* d, const uint32_t* a,
                                         uint32_t b0, uint32_t b1) {
    asm volatile(
        "mma.sync.aligned.m16n8k16.row.col.f32.f16.f16.f32 "
        "{%0,%1,%2,%3},{%4,%5,%6,%7},{%8,%9},{%0,%1,%2,%3};"
        : "+f"(d[0]), "+f"(d[1]), "+f"(d[2]), "+f"(d[3])
        : "r"(a[0]), "r"(a[1]), "r"(a[2]), "r"(a[3]), "r"(b0), "r"(b1));
}
__device__ __forceinline__ float sigf(float x) {
    float e = __expf(-x);
    float d = 1.f + e, r;
    asm("rcp.approx.f32 %0, %1;" : "=f"(r) : "f"(d));
    return r;
}
__device__ __forceinline__ float tanhf_fast(float x) {
    return 2.f * sigf(2.f * x) - 1.f;
}
__device__ __forceinline__ uint32_t ldcg_u32(const __half2* p) {
    uint32_t v;
    asm volatile("ld.global.cg.b32 %0, [%1];" : "=r"(v) : "l"(p));
    return v;
}
__device__ __forceinline__ float2 h2f2(uint32_t h) {
    __half2 hh = *(__half2*)&h;
    return __half22float2(hh);
}
__device__ __forceinline__ void stcs_u32(void* p, uint32_t v) {
    asm volatile("st.global.cs.b32 [%0], %1;" :: "l"(p), "r"(v) : "memory");
}
__device__ __forceinline__ void red_release_add(int* p, int v) {
    asm volatile("red.release.gpu.global.add.s32 [%0], %1;" :: "l"(p), "r"(v) : "memory");
}
__device__ __forceinline__ void st_release(int* p, int v) {
    asm volatile("st.release.gpu.global.s32 [%0], %1;" :: "l"(p), "r"(v) : "memory");
}

// ---------------------------------------------------------------------------
// the persistent kernel
// ---------------------------------------------------------------------------
__global__ __launch_bounds__(NTHREADS, 2)
void qrnn_main(const float* __restrict__ x,
               const float* __restrict__ kern,
               const float* __restrict__ bias)
{
    extern __shared__ char smem[];
    __shared__ int s_work;
    const uint32_t sb = smem_u32(smem);

    const int tid  = threadIdx.x;
    const int wid  = tid >> 5;
    const int lane = tid & 31;

    // ================= phase 0: conversion items ==============================
    while (true) {
        if (tid == 0) s_work = atomicAdd(&g_conv_ctr, 1);
        __syncthreads();
        const int item = s_work;
        __syncthreads();
        if (item >= NCONV) break;

        if (item < KBLKS) {
            // W transpose: kern [K][N3] f32 -> g_wh [N3][K] fp16 (32x32 tile)
            __shared__ float tile[32][33];
            const int bx = item % (N3_ / 32);
            const int by = item / (N3_ / 32);
            const int tx = tid & 31;
            const int ty = tid >> 5;
            #pragma unroll
            for (int j = 0; j < 4; j++) {
                const int k = by * 32 + ty + 8 * j;
                tile[ty + 8 * j][tx] = kern[(size_t)k * N3_ + bx * 32 + tx];
            }
            __syncthreads();
            #pragma unroll
            for (int j = 0; j < 4; j++) {
                const int n = bx * 32 + ty + 8 * j;
                g_wh[(size_t)n * K_ + by * 32 + tx] = __float2half_rn(tile[tx][ty + 8 * j]);
            }
            __syncthreads();
            if (tid == 0) red_release_add(&g_w_cnt, 1);
        } else {
            // x block: rows [xb*128, xb*128+128) -> g_xh fp16
            const int xb = item - KBLKS;
            const size_t base = (size_t)xb * 128 * D_;    // floats
            #pragma unroll 4
            for (int it = 0; it < 64; it++) {
                const size_t i = base + ((size_t)(it * 256 + tid)) * 4;
                float4 v = *(const float4*)(x + i);
                __half2 h0 = __floats2half2_rn(v.x, v.y);
                __half2 h1 = __floats2half2_rn(v.z, v.w);
                *(uint2*)(g_xh + i) = make_uint2(*(uint32_t*)&h0, *(uint32_t*)&h1);
            }
            __syncthreads();
            if (tid == 0) st_release(&g_x_done[xb], 1);
        }
    }

    // ================= phase 1: GEMM tiles ====================================
    const int wm = (wid >> 2) * 64;
    const int wn = (wid & 3) * 32;
    const uint32_t aRowB = (uint32_t)((wm + (lane & 15)) * ROWB + (lane >> 4) * 16);
    const uint32_t bRowB = (uint32_t)(MAT_BYTES
                                      + (wn + ((lane >> 4) & 1) * 8 + (lane & 7)) * ROWB
                                      + ((lane >> 3) & 1) * 16);
    const int arow = tid >> 1;
    const int seg0 = (tid & 1) * 2;

    while (true) {
        if (tid == 0) s_work = atomicAdd(&g_tile_ctr, 1);
        __syncthreads();
        const int tau = s_work;
        if (tau >= NT_TILES) break;

        const int n0 = (tau % NBLK) * BN;
        const int m0 = (tau / NBLK) * BM;
        const int mb = m0 >> 7;
        const int mbp = (mb == 0) ? 0 : (mb - 1);

        // wait for conversion of this tile's inputs
        if (tid == 0) {
            volatile int* wc = &g_w_cnt;
            volatile int* xd = g_x_done;
            while (*wc < KBLKS || !xd[mb] || !xd[mbp]) { __nanosleep(64); }
        }
        __syncthreads();
        __threadfence();

        const int mg = m0 + arow;
        const int avalid = ((mg & (T_ - 1)) != 0);
        const size_t a_prev = avalid ? (size_t)(mg - 1) * D_ : 0;
        const size_t a_cur  = (size_t)mg * D_;
        const size_t b_off  = (size_t)(n0 + arow) * K_;
        const uint32_t dstRow = (uint32_t)(arow * ROWB);

#define LOAD_STAGE(I) do {                                                    \
        const int s_ = (I) & 3;                                               \
        const int kk_ = (I) * BK;                                             \
        const __half* sx_; int asz_;                                          \
        if (kk_ < 512) { sx_ = g_xh + a_prev + kk_; asz_ = avalid ? 16 : 0; } \
        else           { sx_ = g_xh + a_cur + kk_ - 512; asz_ = 16; }         \
        const __half* sw_ = g_wh + b_off + kk_;                               \
        const uint32_t d_ = sb + s_ * STAGE_BYTES + dstRow;                   \
        _Pragma("unroll")                                                     \
        for (int j_ = 0; j_ < 2; j_++) {                                      \
            const int sg_ = seg0 + j_;                                        \
            cp16(d_ + 0*MAT_BYTES + sg_*16, sx_ + sg_*8, asz_);               \
            cp16(d_ + 1*MAT_BYTES + sg_*16, sw_ + sg_*8, 16);                 \
        }                                                                     \
        cp_commit();                                                          \
    } while (0)

        float acc[4][4][4];
        #pragma unroll
        for (int i = 0; i < 4; i++)
            #pragma unroll
            for (int j = 0; j < 4; j++)
                #pragma unroll
                for (int q = 0; q < 4; q++) acc[i][j][q] = 0.f;

        #pragma unroll
        for (int i = 0; i < STAGES - 1; i++) LOAD_STAGE(i);

        for (int i = 0; i < KCHUNKS; i++) {
            asm volatile("cp.async.wait_group %0;" :: "n"(STAGES - 2));
            __syncthreads();

            const uint32_t stg = sb + (i & 3) * STAGE_BYTES;

            // ks0 fragments first
            uint32_t ax0[4][4], bw0[2][4];
            #pragma unroll
            for (int mi = 0; mi < 4; mi++)
                ldm_x4(ax0[mi], stg + aRowB + mi * 16 * ROWB);
            #pragma unroll
            for (int np = 0; np < 2; np++)
                ldm_x4(bw0[np], stg + bRowB + np * 16 * ROWB);

            // prefetch next stage while ks0 fragments land
            const int pf = i + STAGES - 1;
            if (pf < KCHUNKS) LOAD_STAGE(pf);
            else              cp_commit();

            // mma ks0
            #pragma unroll
            for (int mi = 0; mi < 4; mi++)
                #pragma unroll
                for (int nj = 0; nj < 4; nj++) {
                    const int np = nj >> 1, h = (nj & 1) * 2;
                    mma16816(acc[mi][nj], ax0[mi], bw0[np][h], bw0[np][h + 1]);
                }

            // ks1 fragments + mma
            uint32_t ax1[4][4], bw1[2][4];
            #pragma unroll
            for (int mi = 0; mi < 4; mi++)
                ldm_x4(ax1[mi], stg + aRowB + mi * 16 * ROWB + 32);
            #pragma unroll
            for (int np = 0; np < 2; np++)
                ldm_x4(bw1[np], stg + bRowB + np * 16 * ROWB + 32);
            #pragma unroll
            for (int mi = 0; mi < 4; mi++)
                #pragma unroll
                for (int nj = 0; nj < 4; nj++) {
                    const int np = nj >> 1, h = (nj & 1) * 2;
                    mma16816(acc[mi][nj], ax1[mi], bw1[np][h], bw1[np][h + 1]);
                }
        }
        asm volatile("cp.async.wait_group 0;" ::: "memory");

        // ---- epilogue (streaming stores: keep X/W resident in L2)
        const bool is_tanh = (n0 < U_);
        #pragma unroll
        for (int nj = 0; nj < 4; nj++) {
            const int c = n0 + wn + nj * 8 + (lane & 3) * 2;
            const float bb0 = __ldg(bias + c);
            const float bb1 = __ldg(bias + c + 1);
            #pragma unroll
            for (int mi = 0; mi < 4; mi++) {
                const int r = m0 + wm + mi * 16 + (lane >> 2);
                float2 v0, v1;
                v0.x = acc[mi][nj][0] + bb0; v0.y = acc[mi][nj][1] + bb1;
                v1.x = acc[mi][nj][2] + bb0; v1.y = acc[mi][nj][3] + bb1;
                if (is_tanh) {
                    v0.x = tanhf_fast(v0.x); v0.y = tanhf_fast(v0.y);
                    v1.x = tanhf_fast(v1.x); v1.y = tanhf_fast(v1.y);
                } else {
                    v0.x = sigf(v0.x); v0.y = sigf(v0.y);
                    v1.x = sigf(v1.x); v1.y = sigf(v1.y);
                }
                __half2 h0 = __floats2half2_rn(v0.x, v0.y);
                __half2 h1 = __floats2half2_rn(v1.x, v1.y);
                stcs_u32(g_gatesh + (size_t)r * N3_ + c,       *(uint32_t*)&h0);
                stcs_u32(g_gatesh + (size_t)(r + 8) * N3_ + c, *(uint32_t*)&h1);
            }
        }
        __syncthreads();
        if (tid == 0) red_release_add(&g_mb_done[mb], 1);
#undef LOAD_STAGE
    }

    // ================= phase 2: scan pass1 items ==============================
    while (true) {
        if (tid == 0) s_work = (int)atomicAdd(&g_p1_ctr, 1u);
        __syncthreads();
        const int it = s_work;
        __syncthreads();
        if (it >= NP1) break;

        const int b     = it >> 6;
        const int chunk = it & (NCHUNK - 1);
        const int mb    = b * 32 + (chunk >> 1);

        if (tid == 0) {
            volatile int* dp = g_mb_done;
            while (dp[mb] < NBLK) { __nanosleep(128); }
        }
        __syncthreads();
        __threadfence();

        const int u2 = tid;
        const __half2* gh = (const __half2*)g_gatesh;
        size_t base = (size_t)(b * T_ + chunk * TCHUNK) * N3H2 + u2;
        float2 c = make_float2(0.f, 0.f);
        float2 P = make_float2(1.f, 1.f);
        #pragma unroll 8
        for (int s = 0; s < TCHUNK; s++) {
            const float2 z = h2f2(ldcg_u32(gh + base));
            const float2 f = h2f2(ldcg_u32(gh + base + U2));
            c.x = fmaf(f.x, c.x, (1.f - f.x) * z.x);
            c.y = fmaf(f.y, c.y, (1.f - f.y) * z.y);
            P.x *= f.x; P.y *= f.y;
            base += N3H2;
        }
        const int o = ((b * NCHUNK + chunk) * U2 + u2) * 2;
        *(float2*)(g_cend + o) = c;
        *(float2*)(g_P + o)    = P;
    }

    // ================= exit: last CTA resets all counters =====================
    if (tid == 0) {
        __threadfence();
        const int old = atomicAdd(&g_exit_ctr, 1);
        if (old == NCTA - 1) {
            g_conv_ctr = 0;
            g_tile_ctr = 0;
            g_p1_ctr   = 0;
            g_w_cnt    = 0;
            for (int i = 0; i < MBLK; i++) { g_x_done[i] = 0; g_mb_done[i] = 0; }
            __threadfence();
            g_exit_ctr = 0;
        }
    }
}

// ---------------------------------------------------------------------------
// fused scan pass2+3 with depth-4 software prefetch pipeline.
// ---------------------------------------------------------------------------
#define PF 4
__global__ __launch_bounds__(256) void scan_pass23(float* __restrict__ out)
{
    const int blk   = blockIdx.x;          // 0..511
    const int b     = blk >> 6;
    const int chunk = blk & (NCHUNK - 1);
    const int u2    = threadIdx.x;         // 0..255

    // carry-in prefix: sum-scan over chunks [0, chunk)
    float2 c = make_float2(0.f, 0.f);
    #pragma unroll 4
    for (int cc = 0; cc < chunk; cc++) {
        const int o = ((b * NCHUNK + cc) * U2 + u2) * 2;
        const float2 P = *(const float2*)(g_P + o);
        const float2 e = *(const float2*)(g_cend + o);
        c.x = fmaf(P.x, c.x, e.x);
        c.y = fmaf(P.y, c.y, e.y);
    }

    const __half2* gh = (const __half2*)g_gatesh;
    size_t base  = (size_t)(b * T_ + chunk * TCHUNK) * N3H2 + u2;
    size_t obase = (size_t)(b * T_ + chunk * TCHUNK) * U_ + u2 * 2;

    uint32_t zb[PF], fb[PF], ob[PF];
    #pragma unroll
    for (int p = 0; p < PF; p++) {
        const size_t a = base + (size_t)p * N3H2;
        zb[p] = ldcg_u32(gh + a);
        fb[p] = ldcg_u32(gh + a + U2);
        ob[p] = ldcg_u32(gh + a + 2 * U2);
    }

    #pragma unroll 4
    for (int s = 0; s < TCHUNK; s++) {
        const int sl = s & (PF - 1);
        const float2 z = h2f2(zb[sl]);
        const float2 f = h2f2(fb[sl]);
        const float2 o = h2f2(ob[sl]);
        if (s + PF < TCHUNK) {
            const size_t a = base + (size_t)(s + PF) * N3H2;
            zb[sl] = ldcg_u32(gh + a);
            fb[sl] = ldcg_u32(gh + a + U2);
            ob[sl] = ldcg_u32(gh + a + 2 * U2);
        }
        c.x = fmaf(f.x, c.x, (1.f - f.x) * z.x);
        c.y = fmaf(f.y, c.y, (1.f - f.y) * z.y);
        float2 y;
        y.x = o.x * c.x;
        y.y = o.y * c.y;
        *(float2*)(out + obase) = y;
        obase += U_;
    }
}

// ---------------------------------------------------------------------------
extern "C" void kernel_launch(void* const* d_in, const int* in_sizes, int n_in,
                              void* d_out, int out_size)
{
    const float* x    = (const float*)d_in[0];
    const float* kern = (const float*)d_in[1];
    const float* bias = (const float*)d_in[2];
    float* out = (float*)d_out;

    cudaFuncSetAttribute(qrnn_main,
                         cudaFuncAttributeMaxDynamicSharedMemorySize, SMEM_TOTAL);

    qrnn_main<<<NCTA, NTHREADS, SMEM_TOTAL>>>(x, kern, bias);

    scan_pass23<<<B_ * NCHUNK, 256>>>(out);
}

// round 16
// speedup vs baseline: 1.0483x; 1.0483x over previous
#include <cuda_runtime.h>
#include <cuda_fp16.h>
#include <stdint.h>
#include <math.h>

// ---------------------------------------------------------------------------
// QRNN on sm_103. Persistent fused kernel: fp16 HMMA GEMM (128x128 CTA tiles,
// 8 warps x 64x32, 2 CTA/SM), dynamic tiles, scan pass1 fused in the tail;
// pass2+3 fused (128-thr blocks, u2-split). Merged convert kernel.
// Gate stores use st.global.cs to protect X/W L2 residency.
// ---------------------------------------------------------------------------

#define B_   8
#define T_   4096
#define D_   512
#define U_   512
#define N3_  1536
#define K_   1024
#define M_   (B_*T_)

#define BM 128
#define BN 128
#define BK 32
#define KCHUNKS (K_/BK)          // 32
#define STAGES 4
#define NBLK (N3_/BN)            // 12
#define MBLK (M_/BM)             // 256
#define NT_TILES (NBLK*MBLK)     // 3072
#define NCTA 304
#define NTHREADS 256

#define ROWB        80
#define MAT_BYTES   (128*ROWB)                // 10240
#define STAGE_BYTES (2*MAT_BYTES)             // 20480 (X, W)
#define SMEM_TOTAL  (STAGES*STAGE_BYTES)      // 81920

#define NCHUNK 64
#define TCHUNK (T_/NCHUNK)       // 64
#define U2 (U_/2)                // 256
#define N3H2 (N3_/2)             // 768
#define NP1 (B_*NCHUNK)          // 512

// converter grid split
#define KBLKS ((N3_/32)*(K_/32))         // 48*32 = 1536
#define XBLKS ((M_*D_/4)/256)            // 16384

// ---- scratch ----------------------------------------------------------------
__device__ __half g_gatesh[(size_t)M_ * N3_];
__device__ float g_cend [B_*NCHUNK*U_];
__device__ float g_P    [B_*NCHUNK*U_];
__device__ __half g_xh[(size_t)M_ * D_];
__device__ __half g_wh[(size_t)N3_ * K_];
__device__ int g_tile_ctr;
__device__ unsigned g_p1_ctr;
__device__ int g_mb_done[MBLK];

// ---- helpers ------------------------------------------------------------------
__device__ __forceinline__ uint32_t smem_u32(const void* p) {
    uint32_t r;
    asm("{ .reg .u64 t; cvta.to.shared.u64 t, %1; cvt.u32.u64 %0, t; }" : "=r"(r) : "l"(p));
    return r;
}
__device__ __forceinline__ void cp16(uint32_t dst, const void* src, int ssize) {
    asm volatile("cp.async.cg.shared.global [%0], [%1], 16, %2;"
                 :: "r"(dst), "l"(src), "r"(ssize) : "memory");
}
__device__ __forceinline__ void cp_commit() {
    asm volatile("cp.async.commit_group;" ::: "memory");
}
__device__ __forceinline__ void ldm_x4(uint32_t* r, uint32_t addr) {
    asm volatile("ldmatrix.sync.aligned.m8n8.x4.shared.b16 {%0,%1,%2,%3}, [%4];"
                 : "=r"(r[0]), "=r"(r[1]), "=r"(r[2]), "=r"(r[3]) : "r"(addr));
}
__device__ __forceinline__ void mma16816(float* d, const uint32_t* a,
                                         uint32_t b0, uint32_t b1) {
    asm volatile(
        "mma.sync.aligned.m16n8k16.row.col.f32.f16.f16.f32 "
        "{%0,%1,%2,%3},{%4,%5,%6,%7},{%8,%9},{%0,%1,%2,%3};"
        : "+f"(d[0]), "+f"(d[1]), "+f"(d[2]), "+f"(d[3])
        : "r"(a[0]), "r"(a[1]), "r"(a[2]), "r"(a[3]), "r"(b0), "r"(b1));
}
__device__ __forceinline__ float sigf(float x) {
    float e = __expf(-x);
    float d = 1.f + e, r;
    asm("rcp.approx.f32 %0, %1;" : "=f"(r) : "f"(d));
    return r;
}
__device__ __forceinline__ float tanhf_fast(float x) {
    return 2.f * sigf(2.f * x) - 1.f;
}
__device__ __forceinline__ uint32_t ldcg_u32(const __half2* p) {
    uint32_t v;
    asm volatile("ld.global.cg.b32 %0, [%1];" : "=r"(v) : "l"(p));
    return v;
}
__device__ __forceinline__ float2 h2f2(uint32_t h) {
    __half2 hh = *(__half2*)&h;
    return __half22float2(hh);
}
__device__ __forceinline__ void stcs_u32(void* p, uint32_t v) {
    asm volatile("st.global.cs.b32 [%0], %1;" :: "l"(p), "r"(v) : "memory");
}

// ---------------------------------------------------------------------------
// merged converter: blocks [0, KBLKS) transpose the kernel, rest convert x.
// Block KBLKS also resets the work counters.
// ---------------------------------------------------------------------------
__global__ __launch_bounds__(256) void convert_all(const float* __restrict__ x,
                                                   const float* __restrict__ kern) {
    const int bid = blockIdx.x;
    if (bid < KBLKS) {
        __shared__ float tile[32][33];
        const int bx = bid % (N3_ / 32);
        const int by = bid / (N3_ / 32);
        const int tx = threadIdx.x & 31;
        const int ty = threadIdx.x >> 5;
        #pragma unroll
        for (int j = 0; j < 4; j++) {
            const int k = by * 32 + ty + 8 * j;
            tile[ty + 8 * j][tx] = kern[(size_t)k * N3_ + bx * 32 + tx];
        }
        __syncthreads();
        #pragma unroll
        for (int j = 0; j < 4; j++) {
            const int n = bx * 32 + ty + 8 * j;
            g_wh[(size_t)n * K_ + by * 32 + tx] = __float2half_rn(tile[tx][ty + 8 * j]);
        }
        return;
    }
    if (bid == KBLKS) {
        const int t = threadIdx.x;
        if (t == 0) { g_tile_ctr = 0; g_p1_ctr = 0; }
        if (t < MBLK) g_mb_done[t] = 0;
    }
    const size_t i = ((size_t)(bid - KBLKS) * blockDim.x + threadIdx.x) * 4;
    float4 v = *(const float4*)(x + i);
    __half2 h0 = __floats2half2_rn(v.x, v.y);
    __half2 h1 = __floats2half2_rn(v.z, v.w);
    *(uint2*)(g_xh + i) = make_uint2(*(uint32_t*)&h0, *(uint32_t*)&h1);
}

// ---------------------------------------------------------------------------
// fused persistent GEMM + scan pass1
// ---------------------------------------------------------------------------
__global__ __launch_bounds__(NTHREADS, 2)
void gemm_scan1(const float* __restrict__ bias)
{
    extern __shared__ char smem[];
    __shared__ int s_work;
    const uint32_t sb = smem_u32(smem);

    const int tid  = threadIdx.x;
    const int wid  = tid >> 5;
    const int lane = tid & 31;
    const int wm = (wid >> 2) * 64;
    const int wn = (wid & 3) * 32;

    const uint32_t aRowB = (uint32_t)((wm + (lane & 15)) * ROWB + (lane >> 4) * 16);
    const uint32_t bRowB = (uint32_t)(MAT_BYTES
                                      + (wn + ((lane >> 4) & 1) * 8 + (lane & 7)) * ROWB
                                      + ((lane >> 3) & 1) * 16);
    const int arow = tid >> 1;
    const int seg0 = (tid & 1) * 2;

    // ================= phase 1: GEMM tiles ====================================
    while (true) {
        if (tid == 0) s_work = atomicAdd(&g_tile_ctr, 1);
        __syncthreads();
        const int tau = s_work;
        if (tau >= NT_TILES) break;

        const int n0 = (tau % NBLK) * BN;
        const int m0 = (tau / NBLK) * BM;

        const int mg = m0 + arow;
        const int avalid = ((mg & (T_ - 1)) != 0);
        const size_t a_prev = avalid ? (size_t)(mg - 1) * D_ : 0;
        const size_t a_cur  = (size_t)mg * D_;
        const size_t b_off  = (size_t)(n0 + arow) * K_;
        const uint32_t dstRow = (uint32_t)(arow * ROWB);

#define LOAD_STAGE(I) do {                                                    \
        const int s_ = (I) & 3;                                               \
        const int kk_ = (I) * BK;                                             \
        const __half* sx_; int asz_;                                          \
        if (kk_ < 512) { sx_ = g_xh + a_prev + kk_; asz_ = avalid ? 16 : 0; } \
        else           { sx_ = g_xh + a_cur + kk_ - 512; asz_ = 16; }         \
        const __half* sw_ = g_wh + b_off + kk_;                               \
        const uint32_t d_ = sb + s_ * STAGE_BYTES + dstRow;                   \
        _Pragma("unroll")                                                     \
        for (int j_ = 0; j_ < 2; j_++) {                                      \
            const int sg_ = seg0 + j_;                                        \
            cp16(d_ + 0*MAT_BYTES + sg_*16, sx_ + sg_*8, asz_);               \
            cp16(d_ + 1*MAT_BYTES + sg_*16, sw_ + sg_*8, 16);                 \
        }                                                                     \
        cp_commit();                                                          \
    } while (0)

        float acc[4][4][4];
        #pragma unroll
        for (int i = 0; i < 4; i++)
            #pragma unroll
            for (int j = 0; j < 4; j++)
                #pragma unroll
                for (int q = 0; q < 4; q++) acc[i][j][q] = 0.f;

        #pragma unroll
        for (int i = 0; i < STAGES - 1; i++) LOAD_STAGE(i);

        for (int i = 0; i < KCHUNKS; i++) {
            asm volatile("cp.async.wait_group %0;" :: "n"(STAGES - 2));
            __syncthreads();

            const uint32_t stg = sb + (i & 3) * STAGE_BYTES;

            // ks0 fragments first
            uint32_t ax0[4][4], bw0[2][4];
            #pragma unroll
            for (int mi = 0; mi < 4; mi++)
                ldm_x4(ax0[mi], stg + aRowB + mi * 16 * ROWB);
            #pragma unroll
            for (int np = 0; np < 2; np++)
                ldm_x4(bw0[np], stg + bRowB + np * 16 * ROWB);

            // prefetch next stage while ks0 fragments land
            const int pf = i + STAGES - 1;
            if (pf < KCHUNKS) LOAD_STAGE(pf);
            else              cp_commit();

            // mma ks0
            #pragma unroll
            for (int mi = 0; mi < 4; mi++)
                #pragma unroll
                for (int nj = 0; nj < 4; nj++) {
                    const int np = nj >> 1, h = (nj & 1) * 2;
                    mma16816(acc[mi][nj], ax0[mi], bw0[np][h], bw0[np][h + 1]);
                }

            // ks1 fragments + mma
            uint32_t ax1[4][4], bw1[2][4];
            #pragma unroll
            for (int mi = 0; mi < 4; mi++)
                ldm_x4(ax1[mi], stg + aRowB + mi * 16 * ROWB + 32);
            #pragma unroll
            for (int np = 0; np < 2; np++)
                ldm_x4(bw1[np], stg + bRowB + np * 16 * ROWB + 32);
            #pragma unroll
            for (int mi = 0; mi < 4; mi++)
                #pragma unroll
                for (int nj = 0; nj < 4; nj++) {
                    const int np = nj >> 1, h = (nj & 1) * 2;
                    mma16816(acc[mi][nj], ax1[mi], bw1[np][h], bw1[np][h + 1]);
                }
        }
        asm volatile("cp.async.wait_group 0;" ::: "memory");

        // ---- epilogue (evict-first stores: protect X/W residency in L2)
        const bool is_tanh = (n0 < U_);
        #pragma unroll
        for (int nj = 0; nj < 4; nj++) {
            const int c = n0 + wn + nj * 8 + (lane & 3) * 2;
            const float bb0 = __ldg(bias + c);
            const float bb1 = __ldg(bias + c + 1);
            #pragma unroll
            for (int mi = 0; mi < 4; mi++) {
                const int r = m0 + wm + mi * 16 + (lane >> 2);
                float2 v0, v1;
                v0.x = acc[mi][nj][0] + bb0; v0.y = acc[mi][nj][1] + bb1;
                v1.x = acc[mi][nj][2] + bb0; v1.y = acc[mi][nj][3] + bb1;
                if (is_tanh) {
                    v0.x = tanhf_fast(v0.x); v0.y = tanhf_fast(v0.y);
                    v1.x = tanhf_fast(v1.x); v1.y = tanhf_fast(v1.y);
                } else {
                    v0.x = sigf(v0.x); v0.y = sigf(v0.y);
                    v1.x = sigf(v1.x); v1.y = sigf(v1.y);
                }
                __half2 h0 = __floats2half2_rn(v0.x, v0.y);
                __half2 h1 = __floats2half2_rn(v1.x, v1.y);
                stcs_u32(g_gatesh + (size_t)r * N3_ + c,       *(uint32_t*)&h0);
                stcs_u32(g_gatesh + (size_t)(r + 8) * N3_ + c, *(uint32_t*)&h1);
            }
        }
        __threadfence();
        __syncthreads();
        if (tid == 0) atomicAdd(&g_mb_done[m0 >> 7], 1);
#undef LOAD_STAGE
    }

    // ================= phase 2: scan pass1 items ==============================
    while (true) {
        if (tid == 0) s_work = (int)atomicAdd(&g_p1_ctr, 1u);
        __syncthreads();
        const int it = s_work;
        __syncthreads();
        if (it >= NP1) break;

        const int b     = it >> 6;
        const int chunk = it & (NCHUNK - 1);
        const int mb    = b * 32 + (chunk >> 1);

        if (tid == 0) {
            volatile int* dp = g_mb_done;
            while (dp[mb] < NBLK) { __nanosleep(128); }
        }
        __syncthreads();
        __threadfence();

        const int u2 = tid;
        const __half2* gh = (const __half2*)g_gatesh;
        size_t base = (size_t)(b * T_ + chunk * TCHUNK) * N3H2 + u2;
        float2 c = make_float2(0.f, 0.f);
        float2 P = make_float2(1.f, 1.f);
        #pragma unroll 8
        for (int s = 0; s < TCHUNK; s++) {
            const float2 z = h2f2(ldcg_u32(gh + base));
            const float2 f = h2f2(ldcg_u32(gh + base + U2));
            c.x = fmaf(f.x, c.x, (1.f - f.x) * z.x);
            c.y = fmaf(f.y, c.y, (1.f - f.y) * z.y);
            P.x *= f.x; P.y *= f.y;
            base += N3H2;
        }
        const int o = ((b * NCHUNK + chunk) * U2 + u2) * 2;
        *(float2*)(g_cend + o) = c;
        *(float2*)(g_P + o)    = P;
    }
}

// ---------------------------------------------------------------------------
// fused scan pass2+3: 1024 blocks of 128 threads (u2-halves) for finer
// load-balance; depth-4 software prefetch pipeline.
// ---------------------------------------------------------------------------
#define PF 4
__global__ __launch_bounds__(128) void scan_pass23(float* __restrict__ out)
{
    const int blk   = blockIdx.x;          // 0..1023
    const int half  = blk & 1;
    const int chunk = (blk >> 1) & (NCHUNK - 1);
    const int b     = blk >> 7;
    const int u2    = half * 128 + threadIdx.x;   // 0..255

    // carry-in prefix: sum-scan over chunks [0, chunk)
    float2 c = make_float2(0.f, 0.f);
    #pragma unroll 4
    for (int cc = 0; cc < chunk; cc++) {
        const int o = ((b * NCHUNK + cc) * U2 + u2) * 2;
        const float2 P = *(const float2*)(g_P + o);
        const float2 e = *(const float2*)(g_cend + o);
        c.x = fmaf(P.x, c.x, e.x);
        c.y = fmaf(P.y, c.y, e.y);
    }

    const __half2* gh = (const __half2*)g_gatesh;
    size_t base  = (size_t)(b * T_ + chunk * TCHUNK) * N3H2 + u2;
    size_t obase = (size_t)(b * T_ + chunk * TCHUNK) * U_ + u2 * 2;

    uint32_t zb[PF], fb[PF], ob[PF];
    #pragma unroll
    for (int p = 0; p < PF; p++) {
        const size_t a = base + (size_t)p * N3H2;
        zb[p] = ldcg_u32(gh + a);
        fb[p] = ldcg_u32(gh + a + U2);
        ob[p] = ldcg_u32(gh + a + 2 * U2);
    }

    #pragma unroll 4
    for (int s = 0; s < TCHUNK; s++) {
        const int sl = s & (PF - 1);
        const float2 z = h2f2(zb[sl]);
        const float2 f = h2f2(fb[sl]);
        const float2 o = h2f2(ob[sl]);
        if (s + PF < TCHUNK) {
            const size_t a = base + (size_t)(s + PF) * N3H2;
            zb[sl] = ldcg_u32(gh + a);
            fb[sl] = ldcg_u32(gh + a + U2);
            ob[sl] = ldcg_u32(gh + a + 2 * U2);
        }
        c.x = fmaf(f.x, c.x, (1.f - f.x) * z.x);
        c.y = fmaf(f.y, c.y, (1.f - f.y) * z.y);
        float2 y;
        y.x = o.x * c.x;
        y.y = o.y * c.y;
        *(float2*)(out + obase) = y;
        obase += U_;
    }
}

// ---------------------------------------------------------------------------
extern "C" void kernel_launch(void* const* d_in, const int* in_sizes, int n_in,
                              void* d_out, int out_size)
{
    const float* x    = (const float*)d_in[0];
    const float* kern = (const float*)d_in[1];
    const float* bias = (const float*)d_in[2];
    float* out = (float*)d_out;

    cudaFuncSetAttribute(gemm_scan1,
                         cudaFuncAttributeMaxDynamicSharedMemorySize, SMEM_TOTAL);

    convert_all<<<KBLKS + XBLKS, 256>>>(x, kern);

    gemm_scan1<<<NCTA, NTHREADS, SMEM_TOTAL>>>(bias);

    scan_pass23<<<2 * B_ * NCHUNK, 128>>>(out);
}